// round 3
// baseline (speedup 1.0000x reference)
#include <cuda_runtime.h>
#include <cuda_bf16.h>

// Problem constants
#define Bsz   4
#define NODES 51
#define MODAL 4
#define SEQ   256
#define DM    128
#define DK    64

// Precomputed scalars: {A*log2e, C*log2e, wv_mean/3, bv_mean}
__device__ float g_sc[4];

__device__ __forceinline__ float fast_exp2(float x) {
    float y;
    asm("ex2.approx.ftz.f32 %0, %1;" : "=f"(y) : "f"(x));
    return y;
}

// ---- packed f32x2 helpers (sm_103a; ptxas never auto-emits these) ----
typedef unsigned long long u64;
__device__ __forceinline__ u64 pk2(float lo, float hi) {
    u64 r;
    asm("mov.b64 %0, {%1, %2};" : "=l"(r) : "f"(lo), "f"(hi));
    return r;
}
__device__ __forceinline__ void upk2(u64 p, float& lo, float& hi) {
    asm("mov.b64 {%0, %1}, %2;" : "=f"(lo), "=f"(hi) : "l"(p));
}
__device__ __forceinline__ u64 mul2(u64 a, u64 b) {
    u64 r;
    asm("mul.rn.f32x2 %0, %1, %2;" : "=l"(r) : "l"(a), "l"(b));
    return r;
}
__device__ __forceinline__ u64 fma2(u64 a, u64 b, u64 c) {
    u64 r;
    asm("fma.rn.f32x2 %0, %1, %2, %3;" : "=l"(r) : "l"(a), "l"(b), "l"(c));
    return r;
}
__device__ __forceinline__ u64 add2(u64 a, u64 b) {
    u64 r;
    asm("add.rn.f32x2 %0, %1, %2;" : "=l"(r) : "l"(a), "l"(b));
    return r;
}

// ---------------------------------------------------------------------------
// Pre-kernel: collapse W matrices / biases into 4 scalars. (unchanged, ~1.5us)
// ---------------------------------------------------------------------------
__global__ __launch_bounds__(1024) void mmf_scalars_kernel(
    const float* __restrict__ Wq, const float* __restrict__ bq,
    const float* __restrict__ Wk, const float* __restrict__ bk,
    const float* __restrict__ Wv, const float* __restrict__ bv) {
    __shared__ float rs[192];
    __shared__ float red[4][64];

    const int tid  = threadIdx.x;
    const int w    = tid >> 5;
    const int lane = tid & 31;

    float4 vv[6];
#pragma unroll
    for (int rr = 0; rr < 6; rr++) {
        int row = w * 6 + rr;
        int m = row >> 6;
        int k = row & 63;
        const float* base = (m == 0) ? Wq : ((m == 1) ? Wk : Wv);
        vv[rr] = ((const float4*)(base + k * DM))[lane];
    }
#pragma unroll
    for (int rr = 0; rr < 6; rr++) {
        float s = (vv[rr].x + vv[rr].y) + (vv[rr].z + vv[rr].w);
#pragma unroll
        for (int off = 16; off; off >>= 1) s += __shfl_xor_sync(0xffffffff, s, off);
        if (lane == 0) rs[w * 6 + rr] = s;
    }
    __syncthreads();

    if (tid < 64) {
        float wqk = rs[tid], wkk = rs[64 + tid], wvk = rs[128 + tid];
        red[0][tid] = wqk * wkk;
        red[1][tid] = bq[tid] * wkk;
        red[2][tid] = wvk;
        red[3][tid] = bv[tid];
    }
    __syncthreads();
    for (int off = 32; off; off >>= 1) {
        if (tid < off) {
            red[0][tid] += red[0][tid + off];
            red[1][tid] += red[1][tid + off];
            red[2][tid] += red[2][tid + off];
            red[3][tid] += red[3][tid + off];
        }
        __syncthreads();
    }
    if (tid == 0) {
        const float LOG2E = 1.4426950408889634f;
        const float inv_sqrt_dk = 0.125f;
        g_sc[0] = red[0][0] * inv_sqrt_dk * LOG2E;
        g_sc[1] = red[1][0] * inv_sqrt_dk * LOG2E;
        g_sc[2] = red[2][0] * (1.0f / DK) * (1.0f / (MODAL - 1));
        g_sc[3] = red[3][0] * (1.0f / DK);
    }
}

// ---------------------------------------------------------------------------
// Element-pair processors. xt = packed {x_t0, x_t1}; accumulate
//   num += x * 2^(a2*x),  den += 2^(a2*x)
// ---------------------------------------------------------------------------
// MUFU path: 3 fma-pipe insts + 2 MUFU per pair.
__device__ __forceinline__ void mufu_pair(u64 xt, u64 a22, u64& num, u64& den) {
    u64 p = mul2(a22, xt);
    float p0, p1;
    upk2(p, p0, p1);
    float e0 = fast_exp2(p0);
    float e1 = fast_exp2(p1);
    u64 e = pk2(e0, e1);
    num = fma2(xt, e, num);
    den = add2(den, e);
}

// FFMA path: 2^p via magic round-to-int + deg-4 poly on r in [-0.5,0.5]
// + integer exponent insertion. 9 fma-pipe insts + 4 alu per pair, 0 MUFU.
// Poly = Taylor deg-5 economized to deg-4 (r^5 -> Chebyshev fold), err < 1e-5.
__device__ __forceinline__ void poly_pair(u64 xt, u64 a22,
                                          u64 MAGIC2, u64 NEGONE2, u64 C4, u64 C3,
                                          u64 C2, u64 C1, u64 ONE2,
                                          u64& num, u64& den) {
    u64 t  = fma2(a22, xt, MAGIC2);      // RN(p + magic): n in low mantissa bits
    u64 nn = fma2(t, NEGONE2, MAGIC2);   // magic - t = -n (exact)
    u64 r  = fma2(a22, xt, nn);          // r = p - n, in [-0.5, 0.5]
    u64 y  = fma2(r, C4, C3);
    y = fma2(r, y, C2);
    y = fma2(r, y, C1);
    y = fma2(r, y, ONE2);                // y = 2^r in [0.707, 1.414]
    float t0, t1, y0, y1;
    upk2(t, t0, t1);
    upk2(y, y0, y1);
    // bits(t) = 0x4B400000 + n, low 9 bits of magic are 0 => (bits(t)<<23) == n<<23 (mod 2^32)
    unsigned e0 = __float_as_uint(y0) + (__float_as_uint(t0) << 23);
    unsigned e1 = __float_as_uint(y1) + (__float_as_uint(t1) << 23);
    u64 e = pk2(__uint_as_float(e0), __uint_as_float(e1));
    num = fma2(xt, e, num);
    den = add2(den, e);
}

// ---------------------------------------------------------------------------
// Main kernel: one block per (b, n, i). 256 threads, one per s.
// MUFU/FFMA pipe-balanced: per 16 elements, 5 pairs via MUFU (80 mufu-cyc)
// and 3 pairs via poly (84 fma-cyc) per SMSP -> ~5.25 cyc/elem vs 8 before.
// ---------------------------------------------------------------------------
__global__ __launch_bounds__(256, 4) void mmf_fusion_kernel(const float* __restrict__ x,
                                                            float* __restrict__ out) {
    const int bi = blockIdx.x;           // (b*NODES+n)*MODAL + i
    const int i  = bi & (MODAL - 1);
    const int bn = bi >> 2;

    __shared__ float4 sx4[MODAL][SEQ / 4];   // 4 KB tile

    const int tid = threadIdx.x;

    float4 v = ((const float4*)(x + (size_t)bn * (MODAL * SEQ)))[tid];
    ((float4*)sx4)[tid] = v;
    __syncthreads();

    const float A2 = g_sc[0];
    const float C2s = g_sc[1];
    const float Wm = g_sc[2];
    const float Bm = g_sc[3];

    const float xi = ((const float*)sx4)[i * SEQ + tid];
    const float a2 = fmaf(A2, xi, C2s);
    const u64 a22 = pk2(a2, a2);

    // Packed constants (warp-uniform)
    const u64 MAGIC2  = pk2(12582912.0f, 12582912.0f);   // 1.5 * 2^23
    const u64 NEGONE2 = pk2(-1.0f, -1.0f);
    const u64 PC4 = pk2(0.009618129f, 0.009618129f);     // ln2^4/24
    const u64 PC3 = pk2(0.05592078f, 0.05592078f);       // ln2^3/6 + econ
    const u64 PC2 = pk2(0.24022651f, 0.24022651f);       // ln2^2/2
    const u64 PC1 = pk2(0.69312114f, 0.69312114f);       // ln2 - econ
    const u64 ONE2 = pk2(1.0f, 1.0f);

    float acc = 0.f;
#pragma unroll
    for (int j = 0; j < MODAL; j++) {
        if (j == i) continue;
        u64 num_a = 0ull, den_a = 0ull;   // MUFU-path accumulators
        u64 num_b = 0ull, den_b = 0ull;   // poly-path accumulators
        const ulonglong2* __restrict__ row = (const ulonglong2*)&sx4[j][0];
        // 16 iterations x 16 elements (8 pairs: 5 MUFU + 3 poly)
#pragma unroll 4
        for (int it = 0; it < 16; it++) {
            ulonglong2 w0 = row[4 * it + 0];   // LDS.128 broadcast
            ulonglong2 w1 = row[4 * it + 1];
            ulonglong2 w2 = row[4 * it + 2];
            ulonglong2 w3 = row[4 * it + 3];
            mufu_pair(w0.x, a22, num_a, den_a);
            mufu_pair(w0.y, a22, num_a, den_a);
            mufu_pair(w1.x, a22, num_a, den_a);
            mufu_pair(w1.y, a22, num_a, den_a);
            mufu_pair(w2.x, a22, num_a, den_a);
            poly_pair(w2.y, a22, MAGIC2, NEGONE2, PC4, PC3, PC2, PC1, ONE2, num_b, den_b);
            poly_pair(w3.x, a22, MAGIC2, NEGONE2, PC4, PC3, PC2, PC1, ONE2, num_b, den_b);
            poly_pair(w3.y, a22, MAGIC2, NEGONE2, PC4, PC3, PC2, PC1, ONE2, num_b, den_b);
        }
        float n0, n1, n2, n3, d0, d1, d2, d3;
        upk2(num_a, n0, n1);
        upk2(num_b, n2, n3);
        upk2(den_a, d0, d1);
        upk2(den_b, d2, d3);
        acc += __fdividef((n0 + n1) + (n2 + n3), (d0 + d1) + (d2 + d3));
    }

    out[(size_t)bi * SEQ + tid] = fmaf(Wm, acc, Bm);
}

// ---------------------------------------------------------------------------
// Launch
// ---------------------------------------------------------------------------
extern "C" void kernel_launch(void* const* d_in, const int* in_sizes, int n_in,
                              void* d_out, int out_size) {
    const float* x  = (const float*)d_in[0];
    const float* Wq = (const float*)d_in[1];
    const float* bq = (const float*)d_in[2];
    const float* Wk = (const float*)d_in[3];
    const float* bk = (const float*)d_in[4];
    const float* Wv = (const float*)d_in[5];
    const float* bv = (const float*)d_in[6];
    float* out = (float*)d_out;

    mmf_scalars_kernel<<<1, 1024>>>(Wq, bq, Wk, bk, Wv, bv);
    mmf_fusion_kernel<<<Bsz * NODES * MODAL, 256>>>(x, out);
}

// round 4
// speedup vs baseline: 1.9771x; 1.9771x over previous
#include <cuda_runtime.h>
#include <cuda_bf16.h>

// Problem constants
#define Bsz   4
#define NODES 51
#define MODAL 4
#define SEQ   256
#define DM    128
#define DK    64
#define NBN   (Bsz * NODES)          // 204
#define GRID_N 256                   // table nodes per (bn, j)

// Precomputed scalars: {A*log2e, C*log2e, wv_mean/3, bv_mean}
__device__ float g_sc[4];
// Tabulated f_j(a) per (bn, j, node)  (~836 KB scratch, __device__ global per rules)
__device__ float g_F[NBN * MODAL * GRID_N];
// Per-bn grid params: {a_lo, inv_h}
__device__ float g_range[NBN * 2];

__device__ __forceinline__ float fast_exp2(float x) {
    float y;
    asm("ex2.approx.ftz.f32 %0, %1;" : "=f"(y) : "f"(x));
    return y;
}

// ---- packed f32x2 helpers ----
typedef unsigned long long u64;
__device__ __forceinline__ u64 pk2(float lo, float hi) {
    u64 r;
    asm("mov.b64 %0, {%1, %2};" : "=l"(r) : "f"(lo), "f"(hi));
    return r;
}
__device__ __forceinline__ void upk2(u64 p, float& lo, float& hi) {
    asm("mov.b64 {%0, %1}, %2;" : "=f"(lo), "=f"(hi) : "l"(p));
}
__device__ __forceinline__ u64 mul2(u64 a, u64 b) {
    u64 r;
    asm("mul.rn.f32x2 %0, %1, %2;" : "=l"(r) : "l"(a), "l"(b));
    return r;
}
__device__ __forceinline__ u64 fma2(u64 a, u64 b, u64 c) {
    u64 r;
    asm("fma.rn.f32x2 %0, %1, %2, %3;" : "=l"(r) : "l"(a), "l"(b), "l"(c));
    return r;
}
__device__ __forceinline__ u64 add2(u64 a, u64 b) {
    u64 r;
    asm("add.rn.f32x2 %0, %1, %2;" : "=l"(r) : "l"(a), "l"(b));
    return r;
}

// ---------------------------------------------------------------------------
// Kernel A: collapse W matrices / biases into 4 scalars.
// ---------------------------------------------------------------------------
__global__ __launch_bounds__(1024) void mmf_scalars_kernel(
    const float* __restrict__ Wq, const float* __restrict__ bq,
    const float* __restrict__ Wk, const float* __restrict__ bk,
    const float* __restrict__ Wv, const float* __restrict__ bv) {
    __shared__ float rs[192];
    __shared__ float red[4][64];

    const int tid  = threadIdx.x;
    const int w    = tid >> 5;
    const int lane = tid & 31;

    float4 vv[6];
#pragma unroll
    for (int rr = 0; rr < 6; rr++) {
        int row = w * 6 + rr;
        int m = row >> 6;
        int k = row & 63;
        const float* base = (m == 0) ? Wq : ((m == 1) ? Wk : Wv);
        vv[rr] = ((const float4*)(base + k * DM))[lane];
    }
#pragma unroll
    for (int rr = 0; rr < 6; rr++) {
        float s = (vv[rr].x + vv[rr].y) + (vv[rr].z + vv[rr].w);
#pragma unroll
        for (int off = 16; off; off >>= 1) s += __shfl_xor_sync(0xffffffff, s, off);
        if (lane == 0) rs[w * 6 + rr] = s;
    }
    __syncthreads();

    if (tid < 64) {
        float wqk = rs[tid], wkk = rs[64 + tid], wvk = rs[128 + tid];
        red[0][tid] = wqk * wkk;
        red[1][tid] = bq[tid] * wkk;
        red[2][tid] = wvk;
        red[3][tid] = bv[tid];
    }
    __syncthreads();
    for (int off = 32; off; off >>= 1) {
        if (tid < off) {
            red[0][tid] += red[0][tid + off];
            red[1][tid] += red[1][tid + off];
            red[2][tid] += red[2][tid + off];
            red[3][tid] += red[3][tid + off];
        }
        __syncthreads();
    }
    if (tid == 0) {
        const float LOG2E = 1.4426950408889634f;
        const float inv_sqrt_dk = 0.125f;
        g_sc[0] = red[0][0] * inv_sqrt_dk * LOG2E;
        g_sc[1] = red[1][0] * inv_sqrt_dk * LOG2E;
        g_sc[2] = red[2][0] * (1.0f / DK) * (1.0f / (MODAL - 1));
        g_sc[3] = red[3][0] * (1.0f / DK);
    }
}

// ---------------------------------------------------------------------------
// Kernel B: build tables. Block = (bn, j); thread g = grid node.
// f_j(a_g) = sum_t x_j[t] 2^{a_g x_j[t]} / sum_t 2^{a_g x_j[t]}  (exact)
// Grid spans the exact query range [min a(x), max a(x)] over this bn's tile.
// ---------------------------------------------------------------------------
__global__ __launch_bounds__(256, 6) void mmf_table_kernel(const float* __restrict__ x) {
    const int blk = blockIdx.x;          // bn*MODAL + j
    const int j   = blk & (MODAL - 1);
    const int bn  = blk >> 2;

    __shared__ float4 sx4[MODAL][SEQ / 4];   // 4 KB tile
    __shared__ float wmax[8], wmin[8];
    __shared__ float sxr[2];                 // {xmin, xmax}

    const int tid = threadIdx.x;

    float4 v = ((const float4*)(x + (size_t)bn * (MODAL * SEQ)))[tid];
    ((float4*)sx4)[tid] = v;

    // Tile-wide min/max (for grid range)
    float mx = fmaxf(fmaxf(v.x, v.y), fmaxf(v.z, v.w));
    float mn = fminf(fminf(v.x, v.y), fminf(v.z, v.w));
#pragma unroll
    for (int off = 16; off; off >>= 1) {
        mx = fmaxf(mx, __shfl_xor_sync(0xffffffff, mx, off));
        mn = fminf(mn, __shfl_xor_sync(0xffffffff, mn, off));
    }
    const int wid = tid >> 5;
    if ((tid & 31) == 0) { wmax[wid] = mx; wmin[wid] = mn; }
    __syncthreads();
    if (tid == 0) {
        float tmx = wmax[0], tmn = wmin[0];
#pragma unroll
        for (int k = 1; k < 8; k++) {
            tmx = fmaxf(tmx, wmax[k]);
            tmn = fminf(tmn, wmin[k]);
        }
        sxr[0] = tmn;
        sxr[1] = tmx;
    }
    __syncthreads();

    const float A2 = g_sc[0];
    const float C2s = g_sc[1];
    const float a_lo_c = fmaf(A2, sxr[0], C2s);
    const float a_hi_c = fmaf(A2, sxr[1], C2s);
    const float alo = fminf(a_lo_c, a_hi_c);
    const float ahi = fmaxf(a_lo_c, a_hi_c);
    const float h = (ahi - alo) * (1.0f / (GRID_N - 1));

    const float ag = fmaf(h, (float)tid, alo);   // this thread's grid node
    const u64 a22 = pk2(ag, ag);

    u64 num01 = 0ull, num23 = 0ull;
    u64 den01 = 0ull, den23 = 0ull;
    const ulonglong2* __restrict__ row = (const ulonglong2*)&sx4[j][0];
#pragma unroll 8
    for (int t4 = 0; t4 < SEQ / 4; t4++) {
        ulonglong2 xt = row[t4];                 // LDS.128 broadcast
        u64 p01 = mul2(a22, xt.x);
        u64 p23 = mul2(a22, xt.y);
        float p0, p1, p2, p3;
        upk2(p01, p0, p1);
        upk2(p23, p2, p3);
        float e0 = fast_exp2(p0);
        float e1 = fast_exp2(p1);
        float e2 = fast_exp2(p2);
        float e3 = fast_exp2(p3);
        u64 e01 = pk2(e0, e1);
        u64 e23 = pk2(e2, e3);
        num01 = fma2(xt.x, e01, num01);
        num23 = fma2(xt.y, e23, num23);
        den01 = add2(den01, e01);
        den23 = add2(den23, e23);
    }
    float n0, n1, n2, n3, d0, d1, d2, d3;
    upk2(num01, n0, n1);
    upk2(num23, n2, n3);
    upk2(den01, d0, d1);
    upk2(den23, d2, d3);
    g_F[(size_t)blk * GRID_N + tid] =
        __fdividef((n0 + n1) + (n2 + n3), (d0 + d1) + (d2 + d3));

    if (j == 0 && tid == 0) {
        g_range[2 * bn]     = alo;
        g_range[2 * bn + 1] = (ahi > alo) ? (float)(GRID_N - 1) / (ahi - alo) : 0.0f;
    }
}

// ---------------------------------------------------------------------------
// Kernel C: interpolate. Block = bn (1024 threads: i = tid>>8, s = tid&255).
// Catmull-Rom cubic on the per-(bn,j) table; sum over j != i.
// ---------------------------------------------------------------------------
__global__ __launch_bounds__(1024, 1) void mmf_interp_kernel(const float* __restrict__ x,
                                                             float* __restrict__ out) {
    const int bn = blockIdx.x;
    __shared__ float sF[MODAL][GRID_N];      // 4 KB table

    const int tid = threadIdx.x;
    sF[tid >> 8][tid & 255] = g_F[(size_t)bn * (MODAL * GRID_N) + tid];
    __syncthreads();

    const int i = tid >> 8;

    const float xi = x[(size_t)bn * (MODAL * SEQ) + tid];
    const float a2 = fmaf(g_sc[0], xi, g_sc[1]);
    const float alo  = g_range[2 * bn];
    const float invh = g_range[2 * bn + 1];

    float u = (a2 - alo) * invh;
    int i1 = (int)floorf(u);
    i1 = max(0, min(GRID_N - 2, i1));
    float fr = fminf(fmaxf(u - (float)i1, 0.0f), 1.0f);
    const int im  = max(i1 - 1, 0);
    const int ip2 = min(i1 + 2, GRID_N - 1);

    float acc = 0.f;
#pragma unroll
    for (int j = 0; j < MODAL; j++) {
        if (j == i) continue;
        float p0 = sF[j][im];
        float p1 = sF[j][i1];
        float p2 = sF[j][i1 + 1];
        float p3 = sF[j][ip2];
        // Catmull-Rom
        float c3 = 3.0f * (p1 - p2) + (p3 - p0);
        float c2 = 2.0f * p0 - 5.0f * p1 + 4.0f * p2 - p3;
        float c1 = p2 - p0;
        float f = fmaf(0.5f * fr, fmaf(fr, fmaf(fr, c3, c2), c1), p1);
        acc += f;
    }

    out[(size_t)bn * (MODAL * SEQ) + tid] = fmaf(g_sc[2], acc, g_sc[3]);
}

// ---------------------------------------------------------------------------
// Launch
// ---------------------------------------------------------------------------
extern "C" void kernel_launch(void* const* d_in, const int* in_sizes, int n_in,
                              void* d_out, int out_size) {
    const float* x  = (const float*)d_in[0];
    const float* Wq = (const float*)d_in[1];
    const float* bq = (const float*)d_in[2];
    const float* Wk = (const float*)d_in[3];
    const float* bk = (const float*)d_in[4];
    const float* Wv = (const float*)d_in[5];
    const float* bv = (const float*)d_in[6];
    float* out = (float*)d_out;

    mmf_scalars_kernel<<<1, 1024>>>(Wq, bq, Wk, bk, Wv, bv);
    mmf_table_kernel<<<NBN * MODAL, 256>>>(x);
    mmf_interp_kernel<<<NBN, 1024>>>(x, out);
}

// round 5
// speedup vs baseline: 2.7970x; 1.4147x over previous
#include <cuda_runtime.h>
#include <cuda_bf16.h>

// Problem constants
#define Bsz   4
#define NODES 51
#define MODAL 4
#define SEQ   256
#define DM    128
#define DK    64
#define NBN   (Bsz * NODES)          // 204
#define GRID_N 128                   // table nodes per (bn, j)

// Row sums: [0:64)=wq, [64:128)=wk, [128:192)=wv
__device__ float g_rs[192];
// Tabulated f_j(a) per (bn, j, node)
__device__ float g_F[NBN * MODAL * GRID_N];
// Per-bn grid params: {a_lo, inv_h}
__device__ float g_range[NBN * 2];

__device__ __forceinline__ float fast_exp2(float x) {
    float y;
    asm("ex2.approx.ftz.f32 %0, %1;" : "=f"(y) : "f"(x));
    return y;
}

// ---- packed f32x2 helpers ----
typedef unsigned long long u64;
__device__ __forceinline__ u64 pk2(float lo, float hi) {
    u64 r;
    asm("mov.b64 %0, {%1, %2};" : "=l"(r) : "f"(lo), "f"(hi));
    return r;
}
__device__ __forceinline__ void upk2(u64 p, float& lo, float& hi) {
    asm("mov.b64 {%0, %1}, %2;" : "=f"(lo), "=f"(hi) : "l"(p));
}
__device__ __forceinline__ u64 mul2(u64 a, u64 b) {
    u64 r;
    asm("mul.rn.f32x2 %0, %1, %2;" : "=l"(r) : "l"(a), "l"(b));
    return r;
}
__device__ __forceinline__ u64 fma2(u64 a, u64 b, u64 c) {
    u64 r;
    asm("fma.rn.f32x2 %0, %1, %2, %3;" : "=l"(r) : "l"(a), "l"(b), "l"(c));
    return r;
}
__device__ __forceinline__ u64 add2(u64 a, u64 b) {
    u64 r;
    asm("add.rn.f32x2 %0, %1, %2;" : "=l"(r) : "l"(a), "l"(b));
    return r;
}

// A2 = (wq.wk)/sqrt(DK)*log2e, C2 = (bq.wk)/sqrt(DK)*log2e  — warp-collective,
// reads the 192-float rowsum vector (L2-hot) + bq. Call from one warp.
__device__ __forceinline__ void finalize_AC(const float* __restrict__ bq, int lane,
                                            float& A2, float& C2) {
    float wq0 = g_rs[lane],      wq1 = g_rs[lane + 32];
    float wk0 = g_rs[64 + lane], wk1 = g_rs[96 + lane];
    float sA = wq0 * wk0 + wq1 * wk1;
    float sC = bq[lane] * wk0 + bq[lane + 32] * wk1;
#pragma unroll
    for (int off = 16; off; off >>= 1) {
        sA += __shfl_xor_sync(0xffffffff, sA, off);
        sC += __shfl_xor_sync(0xffffffff, sC, off);
    }
    const float K = 0.125f * 1.4426950408889634f;  // log2e/sqrt(64)
    A2 = sA * K;
    C2 = sC * K;
}

// ---------------------------------------------------------------------------
// Kernel A: row sums. 6 blocks x 1024 threads = 192 warps = 192 rows.
// Warp-per-row, float4 lane loads, shfl reduce, no barriers.
// ---------------------------------------------------------------------------
__global__ __launch_bounds__(1024) void mmf_rowsum_kernel(
    const float* __restrict__ Wq, const float* __restrict__ Wk,
    const float* __restrict__ Wv) {
    const int gw   = blockIdx.x * 32 + (threadIdx.x >> 5);  // 0..191
    const int lane = threadIdx.x & 31;
    const int m = gw >> 6;
    const int k = gw & 63;
    const float* base = (m == 0) ? Wq : ((m == 1) ? Wk : Wv);
    float4 v = ((const float4*)(base + k * DM))[lane];
    float s = (v.x + v.y) + (v.z + v.w);
#pragma unroll
    for (int off = 16; off; off >>= 1) s += __shfl_xor_sync(0xffffffff, s, off);
    if (lane == 0) g_rs[gw] = s;
}

// ---------------------------------------------------------------------------
// Kernel B: build tables. Block = (bn, jpair); 256 threads:
//   j = 2*jpair + (tid>>7), node g = tid & 127.
// f_j(a_g) = sum_t x_j[t] 2^{a_g x_j[t]} / sum_t 2^{a_g x_j[t]}  (exact)
// ---------------------------------------------------------------------------
__global__ __launch_bounds__(256, 6) void mmf_table_kernel(const float* __restrict__ x,
                                                           const float* __restrict__ bq) {
    const int blk   = blockIdx.x;        // bn*2 + jpair
    const int jpair = blk & 1;
    const int bn    = blk >> 1;

    __shared__ float4 sx4[MODAL][SEQ / 4];   // 4 KB tile
    __shared__ float wmax[8], wmin[8];
    __shared__ float sAC[2];                 // {A2, C2}
    __shared__ float sxr[2];                 // {xmin, xmax}

    const int tid = threadIdx.x;
    const int wid = tid >> 5;
    const int lane = tid & 31;

    float4 v = ((const float4*)(x + (size_t)bn * (MODAL * SEQ)))[tid];
    ((float4*)sx4)[tid] = v;

    // warp 0: finalize A2/C2 from rowsums (overlaps with min/max below)
    if (wid == 0) {
        float A2, C2;
        finalize_AC(bq, lane, A2, C2);
        if (lane == 0) { sAC[0] = A2; sAC[1] = C2; }
    }

    // Tile-wide min/max
    float mx = fmaxf(fmaxf(v.x, v.y), fmaxf(v.z, v.w));
    float mn = fminf(fminf(v.x, v.y), fminf(v.z, v.w));
#pragma unroll
    for (int off = 16; off; off >>= 1) {
        mx = fmaxf(mx, __shfl_xor_sync(0xffffffff, mx, off));
        mn = fminf(mn, __shfl_xor_sync(0xffffffff, mn, off));
    }
    if (lane == 0) { wmax[wid] = mx; wmin[wid] = mn; }
    __syncthreads();
    if (tid == 0) {
        float tmx = wmax[0], tmn = wmin[0];
#pragma unroll
        for (int k = 1; k < 8; k++) {
            tmx = fmaxf(tmx, wmax[k]);
            tmn = fminf(tmn, wmin[k]);
        }
        sxr[0] = tmn;
        sxr[1] = tmx;
    }
    __syncthreads();

    const float A2 = sAC[0];
    const float C2s = sAC[1];
    const float a_lo_c = fmaf(A2, sxr[0], C2s);
    const float a_hi_c = fmaf(A2, sxr[1], C2s);
    const float alo = fminf(a_lo_c, a_hi_c);
    const float ahi = fmaxf(a_lo_c, a_hi_c);
    const float h = (ahi - alo) * (1.0f / (GRID_N - 1));

    const int j = 2 * jpair + (tid >> 7);    // constant within each warp
    const int g = tid & (GRID_N - 1);
    const float ag = fmaf(h, (float)g, alo);
    const u64 a22 = pk2(ag, ag);

    u64 num01 = 0ull, num23 = 0ull;
    u64 den01 = 0ull, den23 = 0ull;
    const ulonglong2* __restrict__ row = (const ulonglong2*)&sx4[j][0];
#pragma unroll 8
    for (int t4 = 0; t4 < SEQ / 4; t4++) {
        ulonglong2 xt = row[t4];             // LDS.128 broadcast
        u64 p01 = mul2(a22, xt.x);
        u64 p23 = mul2(a22, xt.y);
        float p0, p1, p2, p3;
        upk2(p01, p0, p1);
        upk2(p23, p2, p3);
        float e0 = fast_exp2(p0);
        float e1 = fast_exp2(p1);
        float e2 = fast_exp2(p2);
        float e3 = fast_exp2(p3);
        u64 e01 = pk2(e0, e1);
        u64 e23 = pk2(e2, e3);
        num01 = fma2(xt.x, e01, num01);
        num23 = fma2(xt.y, e23, num23);
        den01 = add2(den01, e01);
        den23 = add2(den23, e23);
    }
    float n0, n1, n2, n3, d0, d1, d2, d3;
    upk2(num01, n0, n1);
    upk2(num23, n2, n3);
    upk2(den01, d0, d1);
    upk2(den23, d2, d3);
    g_F[((size_t)bn * MODAL + j) * GRID_N + g] =
        __fdividef((n0 + n1) + (n2 + n3), (d0 + d1) + (d2 + d3));

    if (jpair == 0 && tid == 0) {
        g_range[2 * bn]     = alo;
        g_range[2 * bn + 1] = (ahi > alo) ? (float)(GRID_N - 1) / (ahi - alo) : 0.0f;
    }
}

// ---------------------------------------------------------------------------
// Kernel C: interpolate. Block = bn (1024 threads: i = tid>>8, s = tid&255).
// Catmull-Rom cubic on the per-(bn,j) table; sum over j != i.
// ---------------------------------------------------------------------------
__global__ __launch_bounds__(1024, 1) void mmf_interp_kernel(const float* __restrict__ x,
                                                             const float* __restrict__ bq,
                                                             const float* __restrict__ bv,
                                                             float* __restrict__ out) {
    const int bn = blockIdx.x;
    __shared__ float sF[MODAL][GRID_N];      // 2 KB table
    __shared__ float sc[4];                  // {A2, C2, Wm, Bm}

    const int tid = threadIdx.x;

    if (tid < MODAL * GRID_N)
        ((float*)sF)[tid] = g_F[(size_t)bn * (MODAL * GRID_N) + tid];

    if (tid < 32) {
        float A2, C2;
        finalize_AC(bq, tid, A2, C2);
        float wv0 = g_rs[128 + tid], wv1 = g_rs[160 + tid];
        float sV = wv0 + wv1;
        float sB = bv[tid] + bv[tid + 32];
#pragma unroll
        for (int off = 16; off; off >>= 1) {
            sV += __shfl_xor_sync(0xffffffff, sV, off);
            sB += __shfl_xor_sync(0xffffffff, sB, off);
        }
        if (tid == 0) {
            sc[0] = A2;
            sc[1] = C2;
            sc[2] = sV * (1.0f / DK) * (1.0f / (MODAL - 1));
            sc[3] = sB * (1.0f / DK);
        }
    }
    __syncthreads();

    const int i = tid >> 8;

    const float xi = x[(size_t)bn * (MODAL * SEQ) + tid];
    const float a2 = fmaf(sc[0], xi, sc[1]);
    const float alo  = g_range[2 * bn];
    const float invh = g_range[2 * bn + 1];

    float u = (a2 - alo) * invh;
    int i1 = (int)floorf(u);
    i1 = max(0, min(GRID_N - 2, i1));
    float fr = fminf(fmaxf(u - (float)i1, 0.0f), 1.0f);
    const int im  = max(i1 - 1, 0);
    const int ip2 = min(i1 + 2, GRID_N - 1);

    float acc = 0.f;
#pragma unroll
    for (int j = 0; j < MODAL; j++) {
        if (j == i) continue;
        float p0 = sF[j][im];
        float p1 = sF[j][i1];
        float p2 = sF[j][i1 + 1];
        float p3 = sF[j][ip2];
        // Catmull-Rom
        float c3 = 3.0f * (p1 - p2) + (p3 - p0);
        float c2 = 2.0f * p0 - 5.0f * p1 + 4.0f * p2 - p3;
        float c1 = p2 - p0;
        float f = fmaf(0.5f * fr, fmaf(fr, fmaf(fr, c3, c2), c1), p1);
        acc += f;
    }

    out[(size_t)bn * (MODAL * SEQ) + tid] = fmaf(sc[2], acc, sc[3]);
}

// ---------------------------------------------------------------------------
// Launch
// ---------------------------------------------------------------------------
extern "C" void kernel_launch(void* const* d_in, const int* in_sizes, int n_in,
                              void* d_out, int out_size) {
    const float* x  = (const float*)d_in[0];
    const float* Wq = (const float*)d_in[1];
    const float* bq = (const float*)d_in[2];
    const float* Wk = (const float*)d_in[3];
    const float* bv = (const float*)d_in[6];
    const float* Wv = (const float*)d_in[5];
    float* out = (float*)d_out;

    mmf_rowsum_kernel<<<6, 1024>>>(Wq, Wk, Wv);
    mmf_table_kernel<<<NBN * 2, 256>>>(x, bq);
    mmf_interp_kernel<<<NBN, 1024>>>(x, bq, bv, out);
}